// round 4
// baseline (speedup 1.0000x reference)
#include <cuda_runtime.h>
#include <cub/cub.cuh>
#include <math.h>

// Problem shapes (fixed): B=4, H=8, S=1024, D=64
#define BH   32
#define SEQ  1024
#define HD   64
#define NFLAT 33554432u   // BH * SEQ * SEQ == 2^25 (index fits in 25 bits)

// ---------------- static device scratch (no allocations allowed) ----------------
static __device__ float    g_w[NFLAT];         // signed -log(rank prob)
static __device__ unsigned g_keys[NFLAT];      // |score| bit patterns (monotonic as uint)
static __device__ unsigned g_vals[NFLAT];      // flat index | (signbit << 31)
static __device__ unsigned g_keys_alt[NFLAT];
static __device__ unsigned g_vals_alt[NFLAT];
static __device__ float    g_qn[BH * SEQ];
static __device__ float    g_kn[BH * SEQ];
static __device__ float    g_rowsum[BH * SEQ];
static __device__ unsigned char g_cub_temp[64u * 1024u * 1024u];

// ---------------- K1: row norms ----------------
__global__ void norms_kernel(const float* __restrict__ q, const float* __restrict__ k,
                             float* __restrict__ qn, float* __restrict__ kn) {
    int r = blockIdx.x * blockDim.x + threadIdx.x;
    if (r >= BH * SEQ) return;
    const float4* qp = (const float4*)(q + (size_t)r * HD);
    const float4* kp = (const float4*)(k + (size_t)r * HD);
    float sq = 0.f, sk = 0.f;
#pragma unroll
    for (int i = 0; i < HD / 4; i++) {
        float4 v = qp[i];
        sq += v.x * v.x + v.y * v.y + v.z * v.z + v.w * v.w;
        float4 w = kp[i];
        sk += w.x * w.x + w.y * w.y + w.z * w.z + w.w * w.w;
    }
    qn[r] = sqrtf(sq) + 1e-5f;
    kn[r] = sqrtf(sk) + 1e-5f;
}

// ---------------- K2: cosine scores -> (key, val) for sort ----------------
// grid (SEQ/64, SEQ/64, BH), block 256. 64x64 output tile, K=64 fully in smem.
__global__ void score_kernel(const float* __restrict__ q, const float* __restrict__ k,
                             const float* __restrict__ qn, const float* __restrict__ kn,
                             unsigned* __restrict__ keys, unsigned* __restrict__ vals) {
    __shared__ float sQ[64][65];
    __shared__ float sK[64][65];
    __shared__ float sqn[64], skn[64];

    int bh = blockIdx.z;
    int i0 = blockIdx.y * 64;
    int j0 = blockIdx.x * 64;
    int t  = threadIdx.x;

    const float* qb = q + ((size_t)bh * SEQ + i0) * HD;
    const float* kb = k + ((size_t)bh * SEQ + j0) * HD;

    for (int l = t; l < 64 * 16; l += 256) {
        int row = l >> 4, c = (l & 15) * 4;
        float4 v = *(const float4*)(qb + row * HD + c);
        sQ[row][c] = v.x; sQ[row][c + 1] = v.y; sQ[row][c + 2] = v.z; sQ[row][c + 3] = v.w;
        float4 w = *(const float4*)(kb + row * HD + c);
        sK[row][c] = w.x; sK[row][c + 1] = w.y; sK[row][c + 2] = w.z; sK[row][c + 3] = w.w;
    }
    if (t < 64) {
        sqn[t] = qn[bh * SEQ + i0 + t];
        skn[t] = kn[bh * SEQ + j0 + t];
    }
    __syncthreads();

    int tx = t & 15, ty = t >> 4;
    float acc[4][4] = {};
#pragma unroll
    for (int kk = 0; kk < 64; kk++) {
        float a[4], b[4];
#pragma unroll
        for (int m = 0; m < 4; m++) a[m] = sQ[ty * 4 + m][kk];
#pragma unroll
        for (int n = 0; n < 4; n++) b[n] = sK[tx * 4 + n][kk];
#pragma unroll
        for (int m = 0; m < 4; m++)
#pragma unroll
            for (int n = 0; n < 4; n++) acc[m][n] += a[m] * b[n];
    }

#pragma unroll
    for (int m = 0; m < 4; m++) {
        int ii = ty * 4 + m;
        float qv = sqn[ii];
        size_t base = ((size_t)bh * SEQ + (i0 + ii)) * SEQ + j0 + tx * 4;
#pragma unroll
        for (int n = 0; n < 4; n++) {
            float s = acc[m][n] / (qv * skn[tx * 4 + n]);
            unsigned bits = __float_as_uint(s);
            keys[base + n] = bits & 0x7fffffffu;                       // |score| pattern
            vals[base + n] = (unsigned)(base + n) | (bits & 0x80000000u); // idx | sign
        }
    }
}

// ---------------- K3: rank scatter (writes SIGNED weight) ----------------
__global__ void rank_scatter_kernel(const unsigned* __restrict__ sortedVal,
                                    float* __restrict__ w) {
    unsigned i = blockIdx.x * blockDim.x + threadIdx.x;
    if (i >= NFLAT) return;
    const float inv_nm1 = 1.0f / (float)(NFLAT - 1u);
    const float inv_n   = 1.0f / (float)NFLAT;
    float prob = fmaf((float)i, inv_nm1, inv_n);
    float wv = -logf(prob);                       // >= 0
    unsigned sv = sortedVal[i];
    unsigned dst = sv & 0x7fffffffu;
    w[dst] = __uint_as_float(__float_as_uint(wv) | (sv & 0x80000000u));
}

// ---------------- K4: per-row L1 sums of w ----------------
__global__ void rowsum_kernel(const float* __restrict__ w, float* __restrict__ rs) {
    int gwarp = (blockIdx.x * blockDim.x + threadIdx.x) >> 5;
    int lane  = threadIdx.x & 31;
    if (gwarp >= BH * SEQ) return;
    const float4* p = (const float4*)(w + (size_t)gwarp * SEQ);
    float s = 0.f;
#pragma unroll
    for (int c = 0; c < 8; c++) {
        float4 v = p[lane + 32 * c];
        s += fabsf(v.x) + fabsf(v.y) + fabsf(v.z) + fabsf(v.w);
    }
#pragma unroll
    for (int o = 16; o; o >>= 1) s += __shfl_xor_sync(0xffffffffu, s, o);
    if (lane == 0) rs[gwarp] = s;
}

// ---------------- K5: out = (w / rowsum) @ V ----------------
// grid (SEQ/64, BH), block 256. 64 rows x 64 (=HD) cols, K loop over SEQ.
__global__ void out_gemm_kernel(const float* __restrict__ w,
                                const float* __restrict__ rs, const float* __restrict__ v,
                                float* __restrict__ out) {
    __shared__ float sW[64][65];
    __shared__ float sV[64][65];
    __shared__ float sinv[64];

    int bh = blockIdx.y;
    int i0 = blockIdx.x * 64;
    int t  = threadIdx.x;
    int tx = t & 15, ty = t >> 4;

    if (t < 64) sinv[t] = 1.0f / rs[bh * SEQ + i0 + t];

    float acc[4][4] = {};
    for (int j0 = 0; j0 < SEQ; j0 += 64) {
        __syncthreads();
        for (int l = t; l < 64 * 16; l += 256) {
            int row = l >> 4, c = (l & 15) * 4;
            size_t base = ((size_t)bh * SEQ + i0 + row) * SEQ + j0 + c;
            float4 wv = *(const float4*)(w + base);
            sW[row][c]     = wv.x;
            sW[row][c + 1] = wv.y;
            sW[row][c + 2] = wv.z;
            sW[row][c + 3] = wv.w;
            float4 vv = *(const float4*)(v + ((size_t)bh * SEQ + j0 + row) * HD + c);
            sV[row][c] = vv.x; sV[row][c + 1] = vv.y; sV[row][c + 2] = vv.z; sV[row][c + 3] = vv.w;
        }
        __syncthreads();
#pragma unroll
        for (int jj = 0; jj < 64; jj++) {
            float a[4], b[4];
#pragma unroll
            for (int m = 0; m < 4; m++) a[m] = sW[ty * 4 + m][jj];
#pragma unroll
            for (int n = 0; n < 4; n++) b[n] = sV[jj][tx * 4 + n];
#pragma unroll
            for (int m = 0; m < 4; m++)
#pragma unroll
                for (int n = 0; n < 4; n++) acc[m][n] += a[m] * b[n];
        }
    }

#pragma unroll
    for (int m = 0; m < 4; m++) {
        int ii = ty * 4 + m;
        float sc = sinv[ii];
        size_t ob = ((size_t)bh * SEQ + i0 + ii) * HD + tx * 4;
#pragma unroll
        for (int n = 0; n < 4; n++) out[ob + n] = acc[m][n] * sc;
    }
}

// ---------------- launch ----------------
extern "C" void kernel_launch(void* const* d_in, const int* in_sizes, int n_in,
                              void* d_out, int out_size) {
    const float* q = (const float*)d_in[0];
    const float* k = (const float*)d_in[1];
    const float* v = (const float*)d_in[2];
    float* out = (float*)d_out;

    float *p_w, *p_qn, *p_kn, *p_rs;
    unsigned *p_keys, *p_vals, *p_keys_alt, *p_vals_alt;
    void* p_tmp;
    cudaGetSymbolAddress((void**)&p_w, g_w);
    cudaGetSymbolAddress((void**)&p_keys, g_keys);
    cudaGetSymbolAddress((void**)&p_vals, g_vals);
    cudaGetSymbolAddress((void**)&p_keys_alt, g_keys_alt);
    cudaGetSymbolAddress((void**)&p_vals_alt, g_vals_alt);
    cudaGetSymbolAddress((void**)&p_qn, g_qn);
    cudaGetSymbolAddress((void**)&p_kn, g_kn);
    cudaGetSymbolAddress((void**)&p_rs, g_rowsum);
    cudaGetSymbolAddress(&p_tmp, g_cub_temp);

    // K1: norms
    norms_kernel<<<(BH * SEQ + 255) / 256, 256>>>(q, k, p_qn, p_kn);

    // K2: scores -> (keys, vals)
    dim3 g2(SEQ / 64, SEQ / 64, BH);
    score_kernel<<<g2, 256>>>(q, k, p_qn, p_kn, p_keys, p_vals);

    // Stable ascending radix sort of |score| bit patterns; payload = idx|sign.
    // Only bits [0,31) matter (bit 31 of key is always 0).
    cub::DoubleBuffer<unsigned> dk(p_keys, p_keys_alt);
    cub::DoubleBuffer<unsigned> dv(p_vals, p_vals_alt);
    size_t tmp_bytes = 0;
    cub::DeviceRadixSort::SortPairs(nullptr, tmp_bytes, dk, dv, (int)NFLAT, 0, 31, (cudaStream_t)0);
    if (tmp_bytes <= sizeof(g_cub_temp)) {
        cub::DeviceRadixSort::SortPairs(p_tmp, tmp_bytes, dk, dv, (int)NFLAT, 0, 31, (cudaStream_t)0);
    }

    // K3: scatter signed -log(rank prob) to original flat positions
    rank_scatter_kernel<<<(NFLAT + 255) / 256, 256>>>(dv.Current(), p_w);

    // K4: per-row L1 sum
    rowsum_kernel<<<(BH * SEQ * 32 + 255) / 256, 256>>>(p_w, p_rs);

    // K5: normalized signed weights @ V
    dim3 g5(SEQ / 64, BH);
    out_gemm_kernel<<<g5, 256>>>(p_w, p_rs, v, out);
}

// round 8
// speedup vs baseline: 2.9424x; 2.9424x over previous
#include <cuda_runtime.h>
#include <cub/cub.cuh>
#include <math.h>

// Problem shapes (fixed): B=4, H=8, S=1024, D=64
#define BH    32
#define SEQ   1024
#define HD    64
#define NFLAT 33554432u    // BH * SEQ * SEQ == 2^25
#define NBINS (1u << 23)   // 23-bit key bins (|score| float bits >> 8)

// ---------------- static device scratch (no allocations allowed) ----------------
static __device__ unsigned g_bits[NFLAT];      // full float bit pattern of score
static __device__ unsigned g_r0[NFLAT];        // within-bin arrival index
static __device__ float    g_w[NFLAT];         // signed -log(rank prob)
static __device__ unsigned g_cnt[NBINS];       // per-bin counts (zeroed each launch)
static __device__ unsigned g_base[NBINS];      // exclusive scan of counts
static __device__ float    g_qn[BH * SEQ];
static __device__ float    g_kn[BH * SEQ];
static __device__ float    g_rowsum[BH * SEQ];
static __device__ unsigned char g_scan_temp[8u * 1024u * 1024u];

// ---------------- K1: row norms ----------------
__global__ void norms_kernel(const float* __restrict__ q, const float* __restrict__ k,
                             float* __restrict__ qn, float* __restrict__ kn) {
    int r = blockIdx.x * blockDim.x + threadIdx.x;
    if (r >= BH * SEQ) return;
    const float4* qp = (const float4*)(q + (size_t)r * HD);
    const float4* kp = (const float4*)(k + (size_t)r * HD);
    float sq = 0.f, sk = 0.f;
#pragma unroll
    for (int i = 0; i < HD / 4; i++) {
        float4 v = qp[i];
        sq += v.x * v.x + v.y * v.y + v.z * v.z + v.w * v.w;
        float4 w = kp[i];
        sk += w.x * w.x + w.y * w.y + w.z * w.z + w.w * w.w;
    }
    qn[r] = sqrtf(sq) + 1e-5f;
    kn[r] = sqrtf(sk) + 1e-5f;
}

// ---------------- K2: cosine scores -> bits + per-bin arrival index ----------------
// grid (SEQ/64, SEQ/64, BH), block 256. 64x64 output tile, K=64 fully in smem.
__global__ void score_kernel(const float* __restrict__ q, const float* __restrict__ k,
                             const float* __restrict__ qn, const float* __restrict__ kn,
                             unsigned* __restrict__ bitsOut, unsigned* __restrict__ r0Out,
                             unsigned* __restrict__ cnt) {
    __shared__ float sQ[64][65];
    __shared__ float sK[64][65];
    __shared__ float sqn[64], skn[64];

    int bh = blockIdx.z;
    int i0 = blockIdx.y * 64;
    int j0 = blockIdx.x * 64;
    int t  = threadIdx.x;

    const float* qb = q + ((size_t)bh * SEQ + i0) * HD;
    const float* kb = k + ((size_t)bh * SEQ + j0) * HD;

    for (int l = t; l < 64 * 16; l += 256) {
        int row = l >> 4, c = (l & 15) * 4;
        float4 v = *(const float4*)(qb + row * HD + c);
        sQ[row][c] = v.x; sQ[row][c + 1] = v.y; sQ[row][c + 2] = v.z; sQ[row][c + 3] = v.w;
        float4 w = *(const float4*)(kb + row * HD + c);
        sK[row][c] = w.x; sK[row][c + 1] = w.y; sK[row][c + 2] = w.z; sK[row][c + 3] = w.w;
    }
    if (t < 64) {
        sqn[t] = qn[bh * SEQ + i0 + t];
        skn[t] = kn[bh * SEQ + j0 + t];
    }
    __syncthreads();

    int tx = t & 15, ty = t >> 4;
    float acc[4][4] = {};
#pragma unroll
    for (int kk = 0; kk < 64; kk++) {
        float a[4], b[4];
#pragma unroll
        for (int m = 0; m < 4; m++) a[m] = sQ[ty * 4 + m][kk];
#pragma unroll
        for (int n = 0; n < 4; n++) b[n] = sK[tx * 4 + n][kk];
#pragma unroll
        for (int m = 0; m < 4; m++)
#pragma unroll
            for (int n = 0; n < 4; n++) acc[m][n] += a[m] * b[n];
    }

#pragma unroll
    for (int m = 0; m < 4; m++) {
        int ii = ty * 4 + m;
        float qv = sqn[ii];
        size_t base = ((size_t)bh * SEQ + (i0 + ii)) * SEQ + j0 + tx * 4;
#pragma unroll
        for (int n = 0; n < 4; n++) {
            float s = acc[m][n] / (qv * skn[tx * 4 + n]);
            unsigned bits = __float_as_uint(s);
            unsigned bin  = (bits & 0x7fffffffu) >> 8;
            unsigned r0   = atomicAdd(&cnt[bin], 1u);
            bitsOut[base + n] = bits;
            r0Out[base + n]   = r0;
        }
    }
}

// ---------------- K3: rank -> signed weight (coalesced) ----------------
__global__ void rank_weight_kernel(const unsigned* __restrict__ bitsIn,
                                   const unsigned* __restrict__ r0In,
                                   const unsigned* __restrict__ base,
                                   float* __restrict__ w) {
    unsigned i4 = (blockIdx.x * blockDim.x + threadIdx.x) * 4u;
    if (i4 >= NFLAT) return;
    const float inv_nm1 = 1.0f / (float)(NFLAT - 1u);
    const float inv_n   = 1.0f / (float)NFLAT;
    uint4 b = *(const uint4*)(bitsIn + i4);
    uint4 r = *(const uint4*)(r0In + i4);
    float4 o;
    {
        unsigned rank = base[(b.x & 0x7fffffffu) >> 8] + r.x;
        float wv = -logf(fmaf((float)rank, inv_nm1, inv_n));
        o.x = __uint_as_float(__float_as_uint(wv) ^ (b.x & 0x80000000u));
    }
    {
        unsigned rank = base[(b.y & 0x7fffffffu) >> 8] + r.y;
        float wv = -logf(fmaf((float)rank, inv_nm1, inv_n));
        o.y = __uint_as_float(__float_as_uint(wv) ^ (b.y & 0x80000000u));
    }
    {
        unsigned rank = base[(b.z & 0x7fffffffu) >> 8] + r.z;
        float wv = -logf(fmaf((float)rank, inv_nm1, inv_n));
        o.z = __uint_as_float(__float_as_uint(wv) ^ (b.z & 0x80000000u));
    }
    {
        unsigned rank = base[(b.w & 0x7fffffffu) >> 8] + r.w;
        float wv = -logf(fmaf((float)rank, inv_nm1, inv_n));
        o.w = __uint_as_float(__float_as_uint(wv) ^ (b.w & 0x80000000u));
    }
    *(float4*)(w + i4) = o;
}

// ---------------- K4: per-row L1 sums of w ----------------
__global__ void rowsum_kernel(const float* __restrict__ w, float* __restrict__ rs) {
    int gwarp = (blockIdx.x * blockDim.x + threadIdx.x) >> 5;
    int lane  = threadIdx.x & 31;
    if (gwarp >= BH * SEQ) return;
    const float4* p = (const float4*)(w + (size_t)gwarp * SEQ);
    float s = 0.f;
#pragma unroll
    for (int c = 0; c < 8; c++) {
        float4 v = p[lane + 32 * c];
        s += fabsf(v.x) + fabsf(v.y) + fabsf(v.z) + fabsf(v.w);
    }
#pragma unroll
    for (int o = 16; o; o >>= 1) s += __shfl_xor_sync(0xffffffffu, s, o);
    if (lane == 0) rs[gwarp] = s;
}

// ---------------- K5: out = (w / rowsum) @ V ----------------
// grid (SEQ/64, BH), block 256.
__global__ void out_gemm_kernel(const float* __restrict__ w,
                                const float* __restrict__ rs, const float* __restrict__ v,
                                float* __restrict__ out) {
    __shared__ float sW[64][65];
    __shared__ float sV[64][65];
    __shared__ float sinv[64];

    int bh = blockIdx.y;
    int i0 = blockIdx.x * 64;
    int t  = threadIdx.x;
    int tx = t & 15, ty = t >> 4;

    if (t < 64) sinv[t] = 1.0f / rs[bh * SEQ + i0 + t];

    float acc[4][4] = {};
    for (int j0 = 0; j0 < SEQ; j0 += 64) {
        __syncthreads();
        for (int l = t; l < 64 * 16; l += 256) {
            int row = l >> 4, c = (l & 15) * 4;
            size_t base = ((size_t)bh * SEQ + i0 + row) * SEQ + j0 + c;
            float4 wv = *(const float4*)(w + base);
            sW[row][c]     = wv.x;
            sW[row][c + 1] = wv.y;
            sW[row][c + 2] = wv.z;
            sW[row][c + 3] = wv.w;
            float4 vv = *(const float4*)(v + ((size_t)bh * SEQ + j0 + row) * HD + c);
            sV[row][c] = vv.x; sV[row][c + 1] = vv.y; sV[row][c + 2] = vv.z; sV[row][c + 3] = vv.w;
        }
        __syncthreads();
#pragma unroll
        for (int jj = 0; jj < 64; jj++) {
            float a[4], b[4];
#pragma unroll
            for (int m = 0; m < 4; m++) a[m] = sW[ty * 4 + m][jj];
#pragma unroll
            for (int n = 0; n < 4; n++) b[n] = sV[jj][tx * 4 + n];
#pragma unroll
            for (int m = 0; m < 4; m++)
#pragma unroll
                for (int n = 0; n < 4; n++) acc[m][n] += a[m] * b[n];
        }
    }

#pragma unroll
    for (int m = 0; m < 4; m++) {
        int ii = ty * 4 + m;
        float sc = sinv[ii];
        size_t ob = ((size_t)bh * SEQ + i0 + ii) * HD + tx * 4;
#pragma unroll
        for (int n = 0; n < 4; n++) out[ob + n] = acc[m][n] * sc;
    }
}

// ---------------- launch ----------------
extern "C" void kernel_launch(void* const* d_in, const int* in_sizes, int n_in,
                              void* d_out, int out_size) {
    const float* q = (const float*)d_in[0];
    const float* k = (const float*)d_in[1];
    const float* v = (const float*)d_in[2];
    float* out = (float*)d_out;

    float *p_w, *p_qn, *p_kn, *p_rs;
    unsigned *p_bits, *p_r0, *p_cnt, *p_base;
    void* p_tmp;
    cudaGetSymbolAddress((void**)&p_w, g_w);
    cudaGetSymbolAddress((void**)&p_bits, g_bits);
    cudaGetSymbolAddress((void**)&p_r0, g_r0);
    cudaGetSymbolAddress((void**)&p_cnt, g_cnt);
    cudaGetSymbolAddress((void**)&p_base, g_base);
    cudaGetSymbolAddress((void**)&p_qn, g_qn);
    cudaGetSymbolAddress((void**)&p_kn, g_kn);
    cudaGetSymbolAddress((void**)&p_rs, g_rowsum);
    cudaGetSymbolAddress(&p_tmp, g_scan_temp);

    // Zero per-bin counters (graph-capturable memset node).
    cudaMemsetAsync(p_cnt, 0, (size_t)NBINS * sizeof(unsigned), (cudaStream_t)0);

    // K1: norms
    norms_kernel<<<(BH * SEQ + 255) / 256, 256>>>(q, k, p_qn, p_kn);

    // K2: scores -> (bits, within-bin arrival index) + bin histogram
    dim3 g2(SEQ / 64, SEQ / 64, BH);
    score_kernel<<<g2, 256>>>(q, k, p_qn, p_kn, p_bits, p_r0, p_cnt);

    // Exclusive scan of bin counts -> global rank base per bin.
    size_t tmp_bytes = 0;
    cub::DeviceScan::ExclusiveSum(nullptr, tmp_bytes, p_cnt, p_base, (int)NBINS, (cudaStream_t)0);
    if (tmp_bytes <= sizeof(g_scan_temp)) {
        cub::DeviceScan::ExclusiveSum(p_tmp, tmp_bytes, p_cnt, p_base, (int)NBINS, (cudaStream_t)0);
    }

    // K3: rank -> signed weight, coalesced write
    rank_weight_kernel<<<(NFLAT / 4 + 255) / 256, 256>>>(p_bits, p_r0, p_base, p_w);

    // K4: per-row L1 sum
    rowsum_kernel<<<(BH * SEQ * 32 + 255) / 256, 256>>>(p_w, p_rs);

    // K5: normalized signed weights @ V
    dim3 g5(SEQ / 64, BH);
    out_gemm_kernel<<<g5, 256>>>(p_w, p_rs, v, out);
}

// round 9
// speedup vs baseline: 3.3788x; 1.1483x over previous
#include <cuda_runtime.h>
#include <cub/cub.cuh>
#include <math.h>

// Problem shapes (fixed): B=4, H=8, S=1024, D=64
#define BH    32
#define SEQ   1024
#define HD    64
#define NFLAT 33554432u       // 2^25
#define SHIFT 10
#define NBINS (1u << (31 - SHIFT))   // 2^21 bins over |score| bit patterns

// ---------------- static device scratch (no allocations allowed) ----------------
static __device__ unsigned g_bits[NFLAT];   // float bit pattern of score
static __device__ unsigned g_r0[NFLAT];     // within-bin arrival index
static __device__ unsigned g_cnt[NBINS];    // per-bin counts (memset to 0 each launch)
static __device__ unsigned g_base[NBINS];   // exclusive scan of counts
static __device__ float    g_qi[BH * SEQ];  // 1 / (|q| + 1e-5)
static __device__ float    g_ki[BH * SEQ];  // 1 / (|k| + 1e-5)
static __device__ unsigned char g_scan_temp[4u * 1024u * 1024u];

// ---------------- K1: reciprocal row norms ----------------
__global__ void norms_kernel(const float* __restrict__ q, const float* __restrict__ k,
                             float* __restrict__ qi, float* __restrict__ ki) {
    int r = blockIdx.x * blockDim.x + threadIdx.x;
    if (r >= BH * SEQ) return;
    const float4* qp = (const float4*)(q + (size_t)r * HD);
    const float4* kp = (const float4*)(k + (size_t)r * HD);
    float sq = 0.f, sk = 0.f;
#pragma unroll
    for (int i = 0; i < HD / 4; i++) {
        float4 v = qp[i];
        sq += v.x * v.x + v.y * v.y + v.z * v.z + v.w * v.w;
        float4 w = kp[i];
        sk += w.x * w.x + w.y * w.y + w.z * w.z + w.w * w.w;
    }
    qi[r] = 1.0f / (sqrtf(sq) + 1e-5f);
    ki[r] = 1.0f / (sqrtf(sk) + 1e-5f);
}

// ---------------- K2: cosine scores -> bits + per-bin arrival index ----------------
// 128x128 tile per 256-thread block (8x8 per thread, 2x2 blocking), K in 2 chunks of 32.
__global__ void __launch_bounds__(256)
score_kernel(const float* __restrict__ q, const float* __restrict__ k,
             const float* __restrict__ qi, const float* __restrict__ ki,
             unsigned* __restrict__ bitsOut, unsigned* __restrict__ r0Out,
             unsigned* __restrict__ cnt) {
    __shared__ float sQ[128][33];
    __shared__ float sK[128][33];
    __shared__ float sqi[128], ski[128];

    int bh = blockIdx.z;
    int i0 = blockIdx.y * 128;
    int j0 = blockIdx.x * 128;
    int t  = threadIdx.x;
    int tx = t & 15, ty = t >> 4;

    const float* qb = q + ((size_t)bh * SEQ + i0) * HD;
    const float* kb = k + ((size_t)bh * SEQ + j0) * HD;

    if (t < 128) {
        sqi[t] = qi[bh * SEQ + i0 + t];
        ski[t] = ki[bh * SEQ + j0 + t];
    }

    float acc[8][8] = {};
#pragma unroll
    for (int kc = 0; kc < 2; kc++) {
        __syncthreads();
        for (int l = t; l < 1024; l += 256) {
            int row = l >> 3, c4 = (l & 7) * 4;
            float4 v = *(const float4*)(qb + row * HD + kc * 32 + c4);
            sQ[row][c4] = v.x; sQ[row][c4 + 1] = v.y; sQ[row][c4 + 2] = v.z; sQ[row][c4 + 3] = v.w;
            float4 w = *(const float4*)(kb + row * HD + kc * 32 + c4);
            sK[row][c4] = w.x; sK[row][c4 + 1] = w.y; sK[row][c4 + 2] = w.z; sK[row][c4 + 3] = w.w;
        }
        __syncthreads();
#pragma unroll
        for (int kk = 0; kk < 32; kk++) {
            float a[8], b[8];
#pragma unroll
            for (int m = 0; m < 8; m++) a[m] = sQ[ty * 4 + (m & 3) + (m >> 2) * 64][kk];
#pragma unroll
            for (int n = 0; n < 8; n++) b[n] = sK[tx * 4 + (n & 3) + (n >> 2) * 64][kk];
#pragma unroll
            for (int m = 0; m < 8; m++)
#pragma unroll
                for (int n = 0; n < 8; n++) acc[m][n] += a[m] * b[n];
        }
    }

#pragma unroll
    for (int m = 0; m < 8; m++) {
        int rm = ty * 4 + (m & 3) + (m >> 2) * 64;
        float qv = sqi[rm];
        size_t rowbase = ((size_t)bh * SEQ + i0 + rm) * SEQ + j0;
#pragma unroll
        for (int h = 0; h < 2; h++) {
            int c0 = tx * 4 + h * 64;
            unsigned bs[4], rr[4];
#pragma unroll
            for (int j = 0; j < 4; j++) {
                float s = acc[m][h * 4 + j] * (qv * ski[c0 + j]);
                unsigned bits = __float_as_uint(s);
                unsigned bin  = (bits & 0x7fffffffu) >> SHIFT;
                bs[j] = bits;
                rr[j] = atomicAdd(&cnt[bin], 1u);
            }
            *(uint4*)(bitsOut + rowbase + c0) = make_uint4(bs[0], bs[1], bs[2], bs[3]);
            *(uint4*)(r0Out   + rowbase + c0) = make_uint4(rr[0], rr[1], rr[2], rr[3]);
        }
    }
}

// ---------------- K3 (fused): w on-the-fly, rowsum in-register, (w/Σ|w|) @ V ----------------
// grid (SEQ/64, BH), block 256. 64x64 W-tile; each block owns 64 full rows.
__global__ void __launch_bounds__(256)
fused_out_kernel(const unsigned* __restrict__ bits, const unsigned* __restrict__ r0,
                 const unsigned* __restrict__ base, const float* __restrict__ v,
                 float* __restrict__ out) {
    __shared__ float sW[64][65];
    __shared__ float sV[64][65];

    int bh = blockIdx.y;
    int i0 = blockIdx.x * 64;
    int t  = threadIdx.x;
    int tx = t & 15, ty = t >> 4;

    const float inv_nm1 = 1.0f / (float)(NFLAT - 1u);
    const float inv_n   = 1.0f / (float)NFLAT;

    float acc[4][4] = {};
    float rs[4] = {};   // full-row sum of |w| (redundant across tx lanes)

    for (int j0 = 0; j0 < SEQ; j0 += 64) {
        __syncthreads();
        for (int l = t; l < 1024; l += 256) {
            int row = l >> 4, c = (l & 15) * 4;
            size_t gbase = ((size_t)bh * SEQ + i0 + row) * SEQ + j0 + c;
            uint4 b = *(const uint4*)(bits + gbase);
            uint4 r = *(const uint4*)(r0 + gbase);
            unsigned rk0 = base[(b.x & 0x7fffffffu) >> SHIFT] + r.x;
            unsigned rk1 = base[(b.y & 0x7fffffffu) >> SHIFT] + r.y;
            unsigned rk2 = base[(b.z & 0x7fffffffu) >> SHIFT] + r.z;
            unsigned rk3 = base[(b.w & 0x7fffffffu) >> SHIFT] + r.w;
            float w0 = -__logf(fmaf((float)rk0, inv_nm1, inv_n));
            float w1 = -__logf(fmaf((float)rk1, inv_nm1, inv_n));
            float w2 = -__logf(fmaf((float)rk2, inv_nm1, inv_n));
            float w3 = -__logf(fmaf((float)rk3, inv_nm1, inv_n));
            sW[row][c]     = __uint_as_float(__float_as_uint(w0) ^ (b.x & 0x80000000u));
            sW[row][c + 1] = __uint_as_float(__float_as_uint(w1) ^ (b.y & 0x80000000u));
            sW[row][c + 2] = __uint_as_float(__float_as_uint(w2) ^ (b.z & 0x80000000u));
            sW[row][c + 3] = __uint_as_float(__float_as_uint(w3) ^ (b.w & 0x80000000u));
            float4 vv = *(const float4*)(v + ((size_t)bh * SEQ + j0 + row) * HD + c);
            sV[row][c] = vv.x; sV[row][c + 1] = vv.y; sV[row][c + 2] = vv.z; sV[row][c + 3] = vv.w;
        }
        __syncthreads();
#pragma unroll
        for (int jj = 0; jj < 64; jj++) {
            float a[4], b[4];
#pragma unroll
            for (int m = 0; m < 4; m++) { a[m] = sW[ty * 4 + m][jj]; rs[m] += fabsf(a[m]); }
#pragma unroll
            for (int n = 0; n < 4; n++) b[n] = sV[jj][tx * 4 + n];
#pragma unroll
            for (int m = 0; m < 4; m++)
#pragma unroll
                for (int n = 0; n < 4; n++) acc[m][n] += a[m] * b[n];
        }
    }

#pragma unroll
    for (int m = 0; m < 4; m++) {
        int ii = ty * 4 + m;
        float sc = 1.0f / rs[m];
        size_t ob = ((size_t)bh * SEQ + i0 + ii) * HD + tx * 4;
#pragma unroll
        for (int n = 0; n < 4; n++) out[ob + n] = acc[m][n] * sc;
    }
}

// ---------------- launch ----------------
extern "C" void kernel_launch(void* const* d_in, const int* in_sizes, int n_in,
                              void* d_out, int out_size) {
    const float* q = (const float*)d_in[0];
    const float* k = (const float*)d_in[1];
    const float* v = (const float*)d_in[2];
    float* out = (float*)d_out;

    float *p_qi, *p_ki;
    unsigned *p_bits, *p_r0, *p_cnt, *p_base;
    void* p_tmp;
    cudaGetSymbolAddress((void**)&p_bits, g_bits);
    cudaGetSymbolAddress((void**)&p_r0, g_r0);
    cudaGetSymbolAddress((void**)&p_cnt, g_cnt);
    cudaGetSymbolAddress((void**)&p_base, g_base);
    cudaGetSymbolAddress((void**)&p_qi, g_qi);
    cudaGetSymbolAddress((void**)&p_ki, g_ki);
    cudaGetSymbolAddress(&p_tmp, g_scan_temp);

    // Zero per-bin counters (graph-capturable memset node).
    cudaMemsetAsync(p_cnt, 0, (size_t)NBINS * sizeof(unsigned), (cudaStream_t)0);

    // K1: reciprocal norms
    norms_kernel<<<(BH * SEQ + 255) / 256, 256>>>(q, k, p_qi, p_ki);

    // K2: scores -> (bits, within-bin arrival index) + bin histogram
    dim3 g2(SEQ / 128, SEQ / 128, BH);
    score_kernel<<<g2, 256>>>(q, k, p_qi, p_ki, p_bits, p_r0, p_cnt);

    // Exclusive scan of bin counts -> global rank base per bin.
    size_t tmp_bytes = 0;
    cub::DeviceScan::ExclusiveSum(nullptr, tmp_bytes, p_cnt, p_base, (int)NBINS, (cudaStream_t)0);
    if (tmp_bytes <= sizeof(g_scan_temp)) {
        cub::DeviceScan::ExclusiveSum(p_tmp, tmp_bytes, p_cnt, p_base, (int)NBINS, (cudaStream_t)0);
    }

    // K3 (fused): rank -> signed weight -> rowsum + GEMM with V, normalized on store
    dim3 g3(SEQ / 64, BH);
    fused_out_kernel<<<g3, 256>>>(p_bits, p_r0, p_base, v, out);
}